// round 17
// baseline (speedup 1.0000x reference)
#include <cuda_runtime.h>
#include <cuda_bf16.h>
#include <cuda_fp16.h>
#include <cstdint>

#define BATCH 2
#define SEQ   2048
#define DMODEL 2048
#define NHEAD 16
#define HDIM  128
#define MROWS (BATCH * SEQ)
#define SCALE 0.08838834764831845f
#define QSCALE (SCALE * 1.4426950408889634f)   // fold log2(e): use exp2f in flash
#define NPERSIST 444                            // 148 SMs x 3 CTAs

// ------------------------- scratch (device globals) -------------------------
__device__ __align__(128) __half g_Xh[(size_t)MROWS * DMODEL];        // X single fp16
__device__ __align__(128) __half g_WqThf[(size_t)DMODEL * DMODEL];    // Wq single fp16
__device__ __align__(128) __half g_WoThf[(size_t)DMODEL * DMODEL];    // Wo single fp16
__device__ __align__(128) __half g_WkThf[(size_t)HDIM * DMODEL];      // Wk single fp16
__device__ __align__(128) __half g_WvThf[(size_t)HDIM * DMODEL];      // Wv single fp16
__device__ __align__(128) __half g_Qh[(size_t)MROWS * DMODEL];        // Q single fp16 (x QSCALE)
__device__ __align__(128) __half g_Kh[(size_t)MROWS * HDIM];          // K single fp16
__device__ __align__(128) __half g_VThf[(size_t)BATCH * HDIM * SEQ];  // V^T single fp16
__device__ __align__(128) __half g_Hh[(size_t)MROWS * DMODEL];        // H single fp16

// ------------------------- PTX helpers --------------------------------------
__device__ __forceinline__ uint32_t cvta_s(const void* p) {
    uint32_t a;
    asm("{ .reg .u64 t; cvta.to.shared.u64 t, %1; cvt.u32.u64 %0, t; }"
        : "=r"(a) : "l"(p));
    return a;
}
__device__ __forceinline__ void cp16(uint32_t s, const void* g) {
    asm volatile("cp.async.cg.shared.global [%0], [%1], 16;" :: "r"(s), "l"(g));
}
__device__ __forceinline__ void ldsm4(uint32_t* r, uint32_t addr) {
    asm volatile("ldmatrix.sync.aligned.m8n8.x4.shared.b16 {%0,%1,%2,%3}, [%4];"
                 : "=r"(r[0]), "=r"(r[1]), "=r"(r[2]), "=r"(r[3]) : "r"(addr));
}
__device__ __forceinline__ void mma_h(float* c, const uint32_t* a, const uint32_t* b) {
    asm volatile(
        "mma.sync.aligned.m16n8k16.row.col.f32.f16.f16.f32 "
        "{%0,%1,%2,%3}, {%4,%5,%6,%7}, {%8,%9}, {%0,%1,%2,%3};"
        : "+f"(c[0]), "+f"(c[1]), "+f"(c[2]), "+f"(c[3])
        : "r"(a[0]), "r"(a[1]), "r"(a[2]), "r"(a[3]), "r"(b[0]), "r"(b[1]));
}
__device__ __forceinline__ uint32_t cvth2(float x0, float x1) {
    uint32_t r;
    asm("cvt.rn.f16x2.f32 %0, %1, %2;" : "=r"(r) : "f"(x1), "f"(x0));
    return r;
}

// ------------------------- single-fp16 GEMM tile body ------------------------
// C[row0:+64, col0:+128] = alpha * A @ B^T. 128 threads, BK=64.
// Stage: A 8K | B 16K = 24K; 2 stages = 48K smem.
// mode 0: fp32 out. mode 3: single fp16 out (Ch).
__device__ __forceinline__ void gemm_h(
    const __half* __restrict__ A, int lda,
    const __half* __restrict__ B, int ldb,
    int K, int row0, int col0, int mode, float alpha,
    float* __restrict__ Cf, __half* __restrict__ Ch, int ldc)
{
    extern __shared__ char dsm[];
    const int tid = threadIdx.x, wid = tid >> 5, l = tid & 31;
    const int wm = (wid & 1) * 32;
    const int wn = (wid >> 1) * 64;
    const uint32_t sbase = cvta_s(dsm);
    const int n = K >> 6;

    float acc[2][8][4] = {};

    auto load_chunk = [&](int k) {
        uint32_t sb = sbase + (uint32_t)(k & 1) * 24576u;
        int k0 = k << 6;
        #pragma unroll
        for (int i = tid; i < 512; i += 128) {            // A: 64 rows x 128B
            int r = i >> 3, c = i & 7;
            uint32_t off = (uint32_t)(r * 128) + ((uint32_t)(c ^ (r & 7)) << 4);
            cp16(sb + off, A + (size_t)(row0 + r) * lda + k0 + c * 8);
        }
        #pragma unroll
        for (int i = tid; i < 1024; i += 128) {           // B: 128 rows x 128B
            int r = i >> 3, c = i & 7;
            uint32_t off = (uint32_t)(r * 128) + ((uint32_t)(c ^ (r & 7)) << 4);
            cp16(sb + 8192u + off, B + (size_t)(col0 + r) * ldb + k0 + c * 8);
        }
        asm volatile("cp.async.commit_group;" ::: "memory");
    };

    load_chunk(0);

    const int at = l >> 3;
    const int arow = ((at & 1) << 3) + (l & 7);
    const uint32_t acolx = (uint32_t)((at >> 1) << 4);
    const int brow = (((l >> 4) & 1) << 3) + (l & 7);
    const uint32_t bcolx = (uint32_t)(((l >> 3) & 1) << 4);

    for (int k = 0; k < n; k++) {
        if (k + 1 < n) {
            load_chunk(k + 1);
            asm volatile("cp.async.wait_group 1;" ::: "memory");
        } else {
            asm volatile("cp.async.wait_group 0;" ::: "memory");
        }
        __syncthreads();

        uint32_t sA = sbase + (uint32_t)(k & 1) * 24576u;
        uint32_t sB = sA + 8192u;
        #pragma unroll
        for (int ks = 0; ks < 4; ks++) {
            const uint32_t koff = (uint32_t)(ks << 5);
            uint32_t bh[4][4];
            #pragma unroll
            for (int nj = 0; nj < 4; nj++) {
                int r = wn + nj * 16 + brow;
                uint32_t c = (koff + bcolx) ^ ((uint32_t)(r & 7) << 4);
                ldsm4(bh[nj], sB + (uint32_t)(r * 128) + c);
            }
            #pragma unroll
            for (int mi = 0; mi < 2; mi++) {
                int r = wm + mi * 16 + arow;
                uint32_t c = (koff + acolx) ^ ((uint32_t)(r & 7) << 4);
                uint32_t ah[4];
                ldsm4(ah, sA + (uint32_t)(r * 128) + c);
                #pragma unroll
                for (int ni = 0; ni < 8; ni++)
                    mma_h(acc[mi][ni], ah, &bh[ni >> 1][(ni & 1) * 2]);
            }
        }
        __syncthreads();
    }

    #pragma unroll
    for (int mi = 0; mi < 2; mi++) {
        #pragma unroll
        for (int ni = 0; ni < 8; ni++) {
            int r0r = row0 + wm + mi * 16 + (l >> 2);
            int col = col0 + wn + ni * 8 + (l & 3) * 2;
            float c0 = acc[mi][ni][0] * alpha, c1 = acc[mi][ni][1] * alpha;
            float c2 = acc[mi][ni][2] * alpha, c3 = acc[mi][ni][3] * alpha;
            if (mode == 0) {
                *(float2*)(Cf + (size_t)r0r * ldc + col) = make_float2(c0, c1);
                *(float2*)(Cf + (size_t)(r0r + 8) * ldc + col) = make_float2(c2, c3);
            } else {
                *(uint32_t*)(Ch + (size_t)r0r * ldc + col) = cvth2(c0, c1);
                *(uint32_t*)(Ch + (size_t)(r0r + 8) * ldc + col) = cvth2(c2, c3);
            }
        }
    }
}

// ------------------------- fused flash attention (persistent) ----------------
// 1024 tiles: t -> p = t>>5 (head-batch), q0 = (t&31)*64. 128 thr, key chunk 32.
// SMEM: Q 16K | 2 stages x (K 8K | V 8K) = 48K. 3 CTAs/SM.
#define NCHUNK (SEQ / 32)
#define SMEM_FLASH 49152

__global__ __launch_bounds__(128, 3) void k_flash() {
    extern __shared__ char dsm[];
    const int tid = threadIdx.x, wid = tid >> 5, l = tid & 31;
    const uint32_t sb = cvta_s(dsm);
    const uint32_t sQ = sb, sSt = sb + 16384u;

    const int at = l >> 3;
    const int arow = ((at & 1) << 3) + (l & 7);
    const uint32_t acolx = (uint32_t)((at >> 1) << 4);
    const int brow = (((l >> 4) & 1) << 3) + (l & 7);
    const uint32_t bcolx = (uint32_t)(((l >> 3) & 1) << 4);
    const int m0 = wid * 16;
    const uint32_t qrowoff = (uint32_t)((m0 + arow) * 256);
    const uint32_t qrswz = (uint32_t)((m0 + arow) & 7) << 4;

    for (int t = blockIdx.x; t < 1024; t += NPERSIST) {
        const int p = t >> 5, b = p >> 4, h = p & 15;
        const int q0 = (t & 31) * 64;
        const __half* Qp = g_Qh + (size_t)b * SEQ * DMODEL + (size_t)h * HDIM;
        const __half* Kp = g_Kh + (size_t)b * SEQ * HDIM;
        const __half* Vp = g_VThf + (size_t)b * HDIM * SEQ;

        // Q tile: 64 rows x 256B, commits with KV0
        #pragma unroll
        for (int i = tid; i < 1024; i += 128) {
            int r = i >> 4, c = i & 15;
            uint32_t off = (uint32_t)(r * 256) + (((uint32_t)(c * 16)) ^ ((uint32_t)(r & 7) << 4));
            cp16(sQ + off, Qp + (size_t)(q0 + r) * DMODEL + c * 8);
        }
        auto loadkv = [&](int kc) {
            uint32_t s = sSt + (uint32_t)(kc & 1) * 16384u;
            int key0 = kc * 32;
            #pragma unroll
            for (int i = tid; i < 512; i += 128) {    // K: 32 rows x 256B
                int r = i >> 4, c = i & 15;
                uint32_t off = (uint32_t)(r * 256) + (((uint32_t)(c * 16)) ^ ((uint32_t)(r & 7) << 4));
                cp16(s + off, Kp + (size_t)(key0 + r) * HDIM + c * 8);
            }
            #pragma unroll
            for (int i = tid; i < 512; i += 128) {    // V^T: 128 rows x 64B
                int r = i >> 2, c = i & 3;
                uint32_t off = (uint32_t)(r * 64) + (((uint32_t)(c * 16)) ^ ((uint32_t)((r >> 1) & 3) << 4));
                cp16(s + 8192u + off, Vp + (size_t)r * SEQ + key0 + c * 8);
            }
            asm volatile("cp.async.commit_group;" ::: "memory");
        };
        loadkv(0);
        loadkv(1);
        asm volatile("cp.async.wait_group 1;" ::: "memory");
        __syncthreads();

        uint32_t qh[8][4];
        #pragma unroll
        for (int ks = 0; ks < 8; ks++)
            ldsm4(qh[ks], sQ + qrowoff + (((uint32_t)(ks << 5) + acolx) ^ qrswz));

        float oacc[16][4] = {};
        float lsum0 = 0.f, lsum1 = 0.f;

        for (int kc = 0; kc < NCHUNK; kc++) {
            uint32_t s = sSt + (uint32_t)(kc & 1) * 16384u;
            uint32_t sK = s, sV = s + 8192u;

            float sacc[4][4] = {};
            #pragma unroll
            for (int ks = 0; ks < 8; ks++) {
                const uint32_t koff = (uint32_t)(ks << 5);
                #pragma unroll
                for (int nj = 0; nj < 2; nj++) {
                    int rr = nj * 16 + brow;
                    uint32_t cc = (koff + bcolx) ^ ((uint32_t)(rr & 7) << 4);
                    uint32_t kh4[4];
                    ldsm4(kh4, sK + (uint32_t)(rr * 256) + cc);
                    mma_h(sacc[nj * 2 + 0], qh[ks], &kh4[0]);
                    mma_h(sacc[nj * 2 + 1], qh[ks], &kh4[2]);
                }
            }

            float ps0 = 0.f, ps1 = 0.f;
            #pragma unroll
            for (int ni = 0; ni < 4; ni++) {
                sacc[ni][0] = exp2f(sacc[ni][0]);
                sacc[ni][1] = exp2f(sacc[ni][1]);
                sacc[ni][2] = exp2f(sacc[ni][2]);
                sacc[ni][3] = exp2f(sacc[ni][3]);
                ps0 += sacc[ni][0] + sacc[ni][1];
                ps1 += sacc[ni][2] + sacc[ni][3];
            }
            lsum0 += ps0;
            lsum1 += ps1;

            #pragma unroll
            for (int j = 0; j < 2; j++) {
                uint32_t ph[4];
                ph[0] = cvth2(sacc[2 * j][0], sacc[2 * j][1]);
                ph[1] = cvth2(sacc[2 * j][2], sacc[2 * j][3]);
                ph[2] = cvth2(sacc[2 * j + 1][0], sacc[2 * j + 1][1]);
                ph[3] = cvth2(sacc[2 * j + 1][2], sacc[2 * j + 1][3]);
                #pragma unroll
                for (int nj = 0; nj < 8; nj++) {
                    int rr = nj * 16 + brow;
                    uint32_t cc = ((uint32_t)(j << 5) + bcolx) ^ ((uint32_t)((rr >> 1) & 3) << 4);
                    uint32_t vh4[4];
                    ldsm4(vh4, sV + (uint32_t)(rr * 64) + cc);
                    mma_h(oacc[nj * 2 + 0], ph, &vh4[0]);
                    mma_h(oacc[nj * 2 + 1], ph, &vh4[2]);
                }
            }

            __syncthreads();                   // done reading buffer kc&1
            if (kc + 2 < NCHUNK) {
                loadkv(kc + 2);
                asm volatile("cp.async.wait_group 1;" ::: "memory");
                __syncthreads();
            } else if (kc + 1 < NCHUNK) {
                asm volatile("cp.async.wait_group 0;" ::: "memory");
                __syncthreads();
            }
        }

        // epilogue: normalize, H single fp16
        lsum0 += __shfl_xor_sync(0xffffffffu, lsum0, 1);
        lsum0 += __shfl_xor_sync(0xffffffffu, lsum0, 2);
        lsum1 += __shfl_xor_sync(0xffffffffu, lsum1, 1);
        lsum1 += __shfl_xor_sync(0xffffffffu, lsum1, 2);
        float inv0 = 1.0f / lsum0, inv1 = 1.0f / lsum1;
        __half* Hp = g_Hh + (size_t)b * SEQ * DMODEL + (size_t)h * HDIM;
        const int r0r = q0 + m0 + (l >> 2);
        const int colb = (l & 3) * 2;
        #pragma unroll
        for (int nj = 0; nj < 16; nj++) {
            int col = nj * 8 + colb;
            *(uint32_t*)(Hp + (size_t)r0r * DMODEL + col) =
                cvth2(oacc[nj][0] * inv0, oacc[nj][1] * inv0);
            *(uint32_t*)(Hp + (size_t)(r0r + 8) * DMODEL + col) =
                cvth2(oacc[nj][2] * inv1, oacc[nj][3] * inv1);
        }
        // safe to start next tile: final compute iteration ended with
        // __syncthreads(), all cp.async groups drained.
    }
}

// ------------------------- fused prep ----------------------------------------
__device__ __forceinline__ void tr_h(const float* __restrict__ src,
                                     __half* __restrict__ dhi,
                                     int R, int C, int bx, int by) {
    __shared__ float t2[32][33];
    int r0 = by * 32, c0 = bx * 32;
    int tx = threadIdx.x & 31, ty = threadIdx.x >> 5;  // 32 x 8
    #pragma unroll
    for (int j = 0; j < 4; j++)
        t2[ty + j * 8][tx] = src[(size_t)(r0 + ty + j * 8) * C + c0 + tx];
    __syncthreads();
    #pragma unroll
    for (int j = 0; j < 4; j++) {
        float v = t2[tx][ty + j * 8];
        size_t o = (size_t)(c0 + ty + j * 8) * R + r0 + tx;
        dhi[o] = __float2half_rn(v);
    }
}

__global__ __launch_bounds__(256) void k_prep(const float* __restrict__ X,
                                              const float* __restrict__ Wq,
                                              const float* __restrict__ Wk,
                                              const float* __restrict__ Wv,
                                              const float* __restrict__ Wo) {
    int z = blockIdx.z;
    if (z == 0) { tr_h(Wq, g_WqThf, DMODEL, DMODEL, blockIdx.x, blockIdx.y); return; }
    if (z == 1) { tr_h(Wo, g_WoThf, DMODEL, DMODEL, blockIdx.x, blockIdx.y); return; }
    if (z == 2) { if (blockIdx.x < 4) tr_h(Wk, g_WkThf, DMODEL, HDIM, blockIdx.x, blockIdx.y); return; }
    if (z == 3) { if (blockIdx.x < 4) tr_h(Wv, g_WvThf, DMODEL, HDIM, blockIdx.x, blockIdx.y); return; }
    // z = 4,5: X -> single fp16
    size_t bid = (size_t)(z - 4) * 4096 + blockIdx.y * 64 + blockIdx.x;
    size_t i = (bid * 256 + threadIdx.x) * 4;
    if (i >= (size_t)MROWS * DMODEL) return;
    float4 v = *(const float4*)(X + i);
    uint2 o;
    o.x = cvth2(v.x, v.y);
    o.y = cvth2(v.z, v.w);
    *(uint2*)(g_Xh + i) = o;
}

// ------------------------- persistent projection kernel ----------------------
// 1152 tiles: <1024 Q-proj, 1024..1087 K-proj, 1088..1151 V^T.
#define SMEM_GEMM 49152

__global__ __launch_bounds__(128, 3) void k_proj() {
    for (int bid = blockIdx.x; bid < 1152; bid += NPERSIST) {
        if (bid < 1024) {
            int x = bid & 15, y = bid >> 4;
            gemm_h(g_Xh, DMODEL, g_WqThf, DMODEL,
                   DMODEL, y * 64, x * 128,
                   3, QSCALE, nullptr, g_Qh, DMODEL);
        } else if (bid < 1088) {
            int y = bid - 1024;
            gemm_h(g_Xh, DMODEL, g_WkThf, DMODEL,
                   DMODEL, y * 64, 0,
                   3, 1.0f, nullptr, g_Kh, HDIM);
        } else {
            int y = bid - 1088;
            int rowblk = y & 1, tb = y >> 1;
            int t0 = tb * 128;
            int b = t0 / SEQ, tl = t0 % SEQ;
            gemm_h(g_WvThf, DMODEL,
                   g_Xh + (size_t)t0 * DMODEL, DMODEL,
                   DMODEL, rowblk * 64, 0,
                   3, 1.0f, nullptr,
                   g_VThf + (size_t)b * HDIM * SEQ + tl, SEQ);
        }
    }
}

__global__ __launch_bounds__(128, 3) void k_outproj(float* __restrict__ out) {
    for (int bid = blockIdx.x; bid < 1024; bid += NPERSIST) {
        int x = bid & 15, y = bid >> 4;
        gemm_h(g_Hh, DMODEL, g_WoThf, DMODEL,
               DMODEL, y * 64, x * 128,
               0, 1.0f, out, nullptr, DMODEL);
    }
}

// ------------------------- launch -------------------------------------------
extern "C" void kernel_launch(void* const* d_in, const int* in_sizes, int n_in,
                              void* d_out, int out_size) {
    const float* X  = (const float*)d_in[0];
    const float* Wq = (const float*)d_in[1];
    const float* Wk = (const float*)d_in[2];
    const float* Wv = (const float*)d_in[3];
    const float* Wo = (const float*)d_in[4];
    float* out = (float*)d_out;

    static int attr_done = 0;
    if (!attr_done) {
        attr_done = 1;
        cudaFuncSetAttribute(k_proj,    cudaFuncAttributeMaxDynamicSharedMemorySize, SMEM_GEMM);
        cudaFuncSetAttribute(k_outproj, cudaFuncAttributeMaxDynamicSharedMemorySize, SMEM_GEMM);
        cudaFuncSetAttribute(k_flash,   cudaFuncAttributeMaxDynamicSharedMemorySize, SMEM_FLASH);
    }

    k_prep<<<dim3(64, 64, 6), 256>>>(X, Wq, Wk, Wv, Wo);
    k_proj<<<NPERSIST, 128, SMEM_GEMM>>>();
    k_flash<<<NPERSIST, 128, SMEM_FLASH>>>();
    k_outproj<<<NPERSIST, 128, SMEM_GEMM>>>(out);
}